// round 16
// baseline (speedup 1.0000x reference)
#include <cuda_runtime.h>

#define N_TRAJ  256
#define T_LEN   1024
#define K_TYPES 1000
#define D_EMB   64
#define EPS     1e-8f

#define N_ROWS      (N_TRAJ * T_LEN)                   // 262144
#define EMB_TOTAL   (N_ROWS * D_EMB)                   // 16777216
#define EMB_BULK4   ((EMB_TOTAL - 4) / 4)              // 4194303 quads at pos 3+4q
#define QPT         4                                  // quads per phase per thread
#define PHASES      2                                  // 2 phases -> 128 rows/block
#define ROWS_PER_BLOCK 128
#define QUADS_PER_BLOCK (256 * QPT * PHASES)           // 2048 quads = 128 rows
#define EMB_BLOCKS  (N_ROWS / ROWS_PER_BLOCK)          // 2048

__device__ int g_reduce_ctr;   // zero-init; reset at end of each launch

// ---------------------------------------------------------------------------
// Fused kernel (R14 structure: QPT=4 x 2 phases; single computed-index LDS).
//   per quad: 1 LDS, 1 aligned LDG.128, 1 SHFL, 1 STG.128.
//   v = emb[pos..pos+3]; hi = table[.][d+1..d+4]; v.yzw = hi.xyz;
//   v.x = previous lane's hi.w (row-wrap at d==3 matches predecessor's
//   wrapped hi); lane 0 loads it scalar.
// ---------------------------------------------------------------------------
__global__ void fused_kernel(const int* __restrict__ event_types,
                             const float* __restrict__ prob_event,
                             const float* __restrict__ intensities,
                             const float* __restrict__ Lambda,
                             const float* __restrict__ input_mask,
                             const float* __restrict__ type_table,
                             float* __restrict__ out,
                             float* __restrict__ out_emb) {
    const int tid = threadIdx.x;

    if (blockIdx.x < N_TRAJ) {
        // ---------------- reduction path (best known) ----------------
        const int n = blockIdx.x;
        const int base = n * T_LEN;

        float m[4], inz[4], p[4];
        #pragma unroll
        for (int i = 0; i < 4; i++) {
            const int t = base + tid + i * 256;
            m[i]   = input_mask[t];
            inz[i] = intensities[t];
            const int e = event_types[t];
            p[i] = __ldcs(&prob_event[(long long)t * K_TYPES + e]);
        }

        float ev = 0.0f, tm = 0.0f;
        #pragma unroll
        for (int i = 0; i < 4; i++) {
            tm = fmaf(__logf(inz[i] + EPS), m[i], tm);
            ev = fmaf(__logf(p[i]   + EPS), m[i], ev);
        }

        __shared__ float s_ev[256];
        __shared__ float s_tm[256];
        s_ev[tid] = ev;
        s_tm[tid] = tm;
        __syncthreads();

        #pragma unroll
        for (int s = 128; s > 0; s >>= 1) {
            if (tid < s) {
                s_ev[tid] += s_ev[tid + s];
                s_tm[tid] += s_tm[tid + s];
            }
            __syncthreads();
        }

        if (tid == 0) {
            const float tnt = s_tm[0] - Lambda[n];
            out[n]              = tnt + s_ev[0];   // ll_N
            out[N_TRAJ + 1 + n] = tnt;             // time_loglik_NT
        }

        __threadfence();
        __shared__ int is_last;
        if (tid == 0) {
            const int v = atomicAdd(&g_reduce_ctr, 1);
            is_last = (v == N_TRAJ - 1);
        }
        __syncthreads();
        if (is_last) {
            __threadfence();
            s_ev[tid] = out[tid];
            __syncthreads();
            #pragma unroll
            for (int s = 128; s > 0; s >>= 1) {
                if (tid < s) s_ev[tid] += s_ev[tid + s];
                __syncthreads();
            }
            if (tid == 0) {
                out[N_TRAJ] = s_ev[0];              // time_loglik
                g_reduce_ctr = 0;                   // reset for graph replay
            }
        }
        return;
    }

    // ---------------- embedding path ----------------
    const int b    = blockIdx.x - N_TRAJ;              // 0 .. 2047
    const int lane = tid & 31;

    // Stage the 129 event indices this block needs (rows 128b .. 128b+128).
    __shared__ int s_idx[129];
    if (tid < 129) {
        const int r = ROWS_PER_BLOCK * b + tid;
        s_idx[tid] = (r < N_ROWS) ? event_types[r] : 0;
    }
    __syncthreads();

    #pragma unroll
    for (int ph = 0; ph < PHASES; ph++) {
        const int qbase = b * QUADS_PER_BLOCK + ph * (256 * QPT) + tid;

        int    pos[QPT];
        bool   ok[QPT];
        float4 hi[QPT];
        float  x0[QPT];

        // Phase A: address math + issue all loads (unconditional, in-bounds;
        // the single out-of-range quad reads s_idx[128]==0 -> safe).
        #pragma unroll
        for (int k = 0; k < QPT; k++) {
            const int q = qbase + k * 256;
            ok[k]  = (q < EMB_BULK4);              // only very last quad fails
            pos[k] = 3 + 4 * q;
            const int lrow = (pos[k] >> 6) - ROWS_PER_BLOCK * b;   // 0..127
            const int d    = pos[k] & (D_EMB - 1);                 // 3,7,...,63
            const bool wrap = (d == D_EMB - 1);

            // single computed-index LDS: the row whose [o..o+3] we need
            const int eb = s_idx[lrow + (wrap ? 1 : 0)];
            const int o  = wrap ? 0 : d + 1;

            hi[k] = __ldg((const float4*)(type_table + eb * D_EMB + o));
            if (lane == 0)
                x0[k] = __ldg(type_table + s_idx[lrow] * D_EMB + d);  // warp head
        }

        // Phase B: shuffle the leading float from the previous lane + store.
        #pragma unroll
        for (int k = 0; k < QPT; k++) {
            float vx = __shfl_up_sync(0xffffffffu, hi[k].w, 1);
            if (lane == 0) vx = x0[k];
            if (ok[k]) {
                float4 v;
                v.x = vx; v.y = hi[k].x; v.z = hi[k].y; v.w = hi[k].z;
                __stcs(reinterpret_cast<float4*>(out_emb + pos[k]), v);
            }
        }
    }

    if (b == 0 && tid == 0) {
        // head pos 0,1,2 (row 0) and tail pos EMB_TOTAL-1
        const int eh = s_idx[0];
        out_emb[0] = __ldg(&type_table[eh * D_EMB + 0]);
        out_emb[1] = __ldg(&type_table[eh * D_EMB + 1]);
        out_emb[2] = __ldg(&type_table[eh * D_EMB + 2]);
        const int lrow = (EMB_TOTAL - 1) >> 6;
        const int el = __ldg(&event_types[lrow]);
        out_emb[EMB_TOTAL - 1] = __ldg(&type_table[el * D_EMB + (D_EMB - 1)]);
    }
}

extern "C" void kernel_launch(void* const* d_in, const int* in_sizes, int n_in,
                              void* d_out, int out_size) {
    const int*   event_types = (const int*)  d_in[0];   // (N, T) int32
    const float* prob_event  = (const float*)d_in[1];   // (N, T, K)
    const float* intensities = (const float*)d_in[2];   // (N, T)
    const float* Lambda      = (const float*)d_in[3];   // (N,)
    const float* input_mask  = (const float*)d_in[4];   // (N, T)
    const float* type_table  = (const float*)d_in[5];   // (K, D)

    float* out = (float*)d_out;
    // Layout: [ll_N (256)] [time_loglik (1)] [time_loglik_NT (256)] [type_emb]
    float* out_emb = out + (N_TRAJ + 1 + N_TRAJ);

    fused_kernel<<<N_TRAJ + EMB_BLOCKS, 256>>>(event_types, prob_event,
                                               intensities, Lambda, input_mask,
                                               type_table, out, out_emb);
}

// round 17
// speedup vs baseline: 1.4508x; 1.4508x over previous
#include <cuda_runtime.h>

#define N_TRAJ  256
#define T_LEN   1024
#define K_TYPES 1000
#define D_EMB   64
#define EPS     1e-8f

#define N_ROWS      (N_TRAJ * T_LEN)                   // 262144
#define EMB_TOTAL   (N_ROWS * D_EMB)                   // 16777216
#define EMB_BULK4   ((EMB_TOTAL - 4) / 4)              // 4194303 quads at pos 3+4q
#define QPT         4                                  // quads per phase per thread
#define PHASES      2                                  // 2 phases -> 128 rows/block
#define ROWS_PER_BLOCK 128
#define QUADS_PER_BLOCK (256 * QPT * PHASES)           // 2048 quads = 128 rows
#define EMB_BLOCKS  (N_ROWS / ROWS_PER_BLOCK)          // 2048

__device__ int g_reduce_ctr;   // zero-init; reset at end of each launch

// ---------------------------------------------------------------------------
// Fused kernel (R14 exact — best measured at 19.2us):
//   blocks [0, 256)          : per-trajectory reduction (4 events/thread,
//                              batched gathers); last-done block folds the
//                              scalar sum deterministically.
//   blocks [256, 256+2048)   : embedding gather, 128 rows/block in 2 phases.
//   Per quad: 1 LDG.128 + 1 SHFL + 1 STG.128 __stcs.
//   v = emb[pos..pos+3]; hi = table[.][d+1..d+4]; v.yzw = hi.xyz;
//   v.x = previous lane's hi.w (row-wrap at d==3 matches the predecessor's
//   wrapped hi); lane 0 loads it scalar.
// ---------------------------------------------------------------------------
__global__ void fused_kernel(const int* __restrict__ event_types,
                             const float* __restrict__ prob_event,
                             const float* __restrict__ intensities,
                             const float* __restrict__ Lambda,
                             const float* __restrict__ input_mask,
                             const float* __restrict__ type_table,
                             float* __restrict__ out,
                             float* __restrict__ out_emb) {
    const int tid = threadIdx.x;

    if (blockIdx.x < N_TRAJ) {
        // ---------------- reduction path (best known) ----------------
        const int n = blockIdx.x;
        const int base = n * T_LEN;

        float m[4], inz[4], p[4];
        #pragma unroll
        for (int i = 0; i < 4; i++) {
            const int t = base + tid + i * 256;
            m[i]   = input_mask[t];
            inz[i] = intensities[t];
            const int e = event_types[t];
            p[i] = __ldcs(&prob_event[(long long)t * K_TYPES + e]);
        }

        float ev = 0.0f, tm = 0.0f;
        #pragma unroll
        for (int i = 0; i < 4; i++) {
            tm = fmaf(__logf(inz[i] + EPS), m[i], tm);
            ev = fmaf(__logf(p[i]   + EPS), m[i], ev);
        }

        __shared__ float s_ev[256];
        __shared__ float s_tm[256];
        s_ev[tid] = ev;
        s_tm[tid] = tm;
        __syncthreads();

        #pragma unroll
        for (int s = 128; s > 0; s >>= 1) {
            if (tid < s) {
                s_ev[tid] += s_ev[tid + s];
                s_tm[tid] += s_tm[tid + s];
            }
            __syncthreads();
        }

        if (tid == 0) {
            const float tnt = s_tm[0] - Lambda[n];
            out[n]              = tnt + s_ev[0];   // ll_N
            out[N_TRAJ + 1 + n] = tnt;             // time_loglik_NT
        }

        __threadfence();
        __shared__ int is_last;
        if (tid == 0) {
            const int v = atomicAdd(&g_reduce_ctr, 1);
            is_last = (v == N_TRAJ - 1);
        }
        __syncthreads();
        if (is_last) {
            __threadfence();
            s_ev[tid] = out[tid];
            __syncthreads();
            #pragma unroll
            for (int s = 128; s > 0; s >>= 1) {
                if (tid < s) s_ev[tid] += s_ev[tid + s];
                __syncthreads();
            }
            if (tid == 0) {
                out[N_TRAJ] = s_ev[0];              // time_loglik
                g_reduce_ctr = 0;                   // reset for graph replay
            }
        }
        return;
    }

    // ---------------- embedding path ----------------
    const int b    = blockIdx.x - N_TRAJ;              // 0 .. 2047
    const int lane = tid & 31;

    // Stage the 129 event indices this block needs (rows 128b .. 128b+128).
    __shared__ int s_idx[129];
    if (tid < 129) {
        const int r = ROWS_PER_BLOCK * b + tid;
        s_idx[tid] = (r < N_ROWS) ? event_types[r] : 0;
    }
    __syncthreads();

    #pragma unroll
    for (int ph = 0; ph < PHASES; ph++) {
        const int qbase = b * QUADS_PER_BLOCK + ph * (256 * QPT) + tid;

        int    pos[QPT];
        bool   ok[QPT];
        float4 hi[QPT];
        float  x0[QPT];

        // Phase A: address math + issue all loads (unconditional, in-bounds).
        #pragma unroll
        for (int k = 0; k < QPT; k++) {
            const int q = qbase + k * 256;
            ok[k]  = (q < EMB_BULK4);              // only very last quad fails
            pos[k] = 3 + 4 * q;
            const int lrow = (pos[k] >> 6) - ROWS_PER_BLOCK * b;   // 0..127
            const int d    = pos[k] & (D_EMB - 1);                 // 3,7,...,63

            const int e  = s_idx[lrow];
            const int eb = (d == D_EMB - 1) ? s_idx[lrow + 1] : e;
            const int o  = (d == D_EMB - 1) ? 0 : d + 1;

            hi[k] = __ldg((const float4*)(type_table + eb * D_EMB + o));
            if (lane == 0)
                x0[k] = __ldg(type_table + e * D_EMB + d);   // warp-head only
        }

        // Phase B: shuffle the leading float from the previous lane + store.
        #pragma unroll
        for (int k = 0; k < QPT; k++) {
            float vx = __shfl_up_sync(0xffffffffu, hi[k].w, 1);
            if (lane == 0) vx = x0[k];
            if (ok[k]) {
                float4 v;
                v.x = vx; v.y = hi[k].x; v.z = hi[k].y; v.w = hi[k].z;
                __stcs(reinterpret_cast<float4*>(out_emb + pos[k]), v);
            }
        }
    }

    if (b == 0 && tid == 0) {
        // head pos 0,1,2 (row 0) and tail pos EMB_TOTAL-1
        const int eh = s_idx[0];
        out_emb[0] = __ldg(&type_table[eh * D_EMB + 0]);
        out_emb[1] = __ldg(&type_table[eh * D_EMB + 1]);
        out_emb[2] = __ldg(&type_table[eh * D_EMB + 2]);
        const int lrow = (EMB_TOTAL - 1) >> 6;
        const int el = __ldg(&event_types[lrow]);
        out_emb[EMB_TOTAL - 1] = __ldg(&type_table[el * D_EMB + (D_EMB - 1)]);
    }
}

extern "C" void kernel_launch(void* const* d_in, const int* in_sizes, int n_in,
                              void* d_out, int out_size) {
    const int*   event_types = (const int*)  d_in[0];   // (N, T) int32
    const float* prob_event  = (const float*)d_in[1];   // (N, T, K)
    const float* intensities = (const float*)d_in[2];   // (N, T)
    const float* Lambda      = (const float*)d_in[3];   // (N,)
    const float* input_mask  = (const float*)d_in[4];   // (N, T)
    const float* type_table  = (const float*)d_in[5];   // (K, D)

    float* out = (float*)d_out;
    // Layout: [ll_N (256)] [time_loglik (1)] [time_loglik_NT (256)] [type_emb]
    float* out_emb = out + (N_TRAJ + 1 + N_TRAJ);

    fused_kernel<<<N_TRAJ + EMB_BLOCKS, 256>>>(event_types, prob_event,
                                               intensities, Lambda, input_mask,
                                               type_table, out, out_emb);
}